// round 11
// baseline (speedup 1.0000x reference)
#include <cuda_runtime.h>
#include <cstdint>
#include <math.h>

// Problem constants
#define BATCH 4
#define NN    3000
#define FF    128

// ---------------- scratch (no allocations allowed) ----------------
__device__ __align__(128) float g_dis[BATCH * NN];        // d^{-1/2}
__device__ __align__(128) float g_xs [BATCH * NN * FF];   // tf32-rounded dis_j * x[j,f]

// ---------------- helpers ----------------
__device__ __forceinline__ uint32_t smem_u32(const void* p) {
    uint32_t a;
    asm("{ .reg .u64 t; cvta.to.shared.u64 t, %1; cvt.u32.u64 %0, t; }" : "=r"(a) : "l"(p));
    return a;
}
__device__ __forceinline__ unsigned f2tf(float f) {
    unsigned u;
    asm("cvt.rna.tf32.f32 %0, %1;" : "=r"(u) : "f"(f));
    return u;
}
__device__ __forceinline__ void cp16(uint32_t dst, const void* src, int bytes) {
    asm volatile("cp.async.cg.shared.global [%0], [%1], 16, %2;"
                 :: "r"(dst), "l"(src), "r"(bytes));
}
__device__ __forceinline__ void cp_commit() { asm volatile("cp.async.commit_group;" ::: "memory"); }

__device__ __forceinline__ void mma_tf32_frag(float* c, const unsigned* a, unsigned b0, unsigned b1) {
    asm volatile(
        "mma.sync.aligned.m16n8k8.row.col.f32.tf32.tf32.f32 "
        "{%0,%1,%2,%3}, {%4,%5,%6,%7}, {%8,%9}, {%0,%1,%2,%3};"
        : "+f"(c[0]), "+f"(c[1]), "+f"(c[2]), "+f"(c[3])
        : "r"(a[0]), "r"(a[1]), "r"(a[2]), "r"(a[3]), "r"(b0), "r"(b1));
}

// ---------------- Kernel 1: warp-per-row  deg -> d^{-1/2}, xs = tf32(dis_j*x) ----------------
__global__ __launch_bounds__(256) void k_rowstats(const float* __restrict__ adj,
                                                  const float* __restrict__ x) {
    int warp = threadIdx.x >> 5;
    int lane = threadIdx.x & 31;
    int row  = blockIdx.x * 8 + warp;          // 12000 rows, grid 1500
    const float4* a4 = reinterpret_cast<const float4*>(adj + (size_t)row * NN);

    float s = 0.f;
    #pragma unroll 4
    for (int i = lane; i < NN / 4; i += 32) {
        float4 v = a4[i];
        s += (v.x + v.y) + (v.z + v.w);
    }
    #pragma unroll
    for (int o = 16; o > 0; o >>= 1) s += __shfl_down_sync(0xffffffffu, s, o);
    float d = rsqrtf(__shfl_sync(0xffffffffu, s, 0) + 1.0f);
    if (lane == 0) g_dis[row] = d;

    float4 v = reinterpret_cast<const float4*>(x + (size_t)row * FF)[lane];
    v.x = __uint_as_float(f2tf(v.x * d));
    v.y = __uint_as_float(f2tf(v.y * d));
    v.z = __uint_as_float(f2tf(v.z * d));
    v.w = __uint_as_float(f2tf(v.w * d));
    reinterpret_cast<float4*>(g_xs + (size_t)row * FF)[lane] = v;
}

// ---------------- Kernel 2: fully fused aggregation + output ----------------
// BMM=48, 128 threads (4 warps), warp tile 48x32 (column-disjoint warps).
// 2 CTAs/SM, 252 CTAs -> full-chip wave with cross-CTA stall covering.
#define BMM     48
#define BKK     32
#define NT      ((NN + BKK - 1) / BKK)     // 94
#define STAGES  4
#define APITCH  36                          // (4g+s)%32 distinct
#define BPITCH  136                         // (8s+col)%32 distinct
#define S2PITCH 132                         // (4g+s)%32 distinct

#define AS_STG_F (BMM * APITCH)             // 1728
#define BS_STG_F (BKK * BPITCH)             // 4352
#define AS_OFF_F 0
#define BS_OFF_F (STAGES * AS_STG_F)        // 6912
#define SMEM_F   (BS_OFF_F + STAGES * BS_STG_F)  // 24320 floats = 97280 B
// epilogue reuse: S2 at 0 (48*132=6336), theta at 6336 (128*136=17408) -> 23744 <= 24320
#define S2_OFF_F 0
#define TH_OFF_F 6336

#define NTHR 128

__global__ __launch_bounds__(NTHR, 2)
void k_agg(const float* __restrict__ adj,
           const float* __restrict__ h0g,
           const float* __restrict__ theta,
           const float* __restrict__ lamda_p,
           const float* __restrict__ alpha_p,
           const int* __restrict__ l_p,
           float* __restrict__ out) {
    extern __shared__ __align__(16) float dsm[];

    const int b   = blockIdx.y;
    const int m0  = blockIdx.x * BMM;
    const int tid = threadIdx.x;
    const int wid = tid >> 5, lane = tid & 31;
    const int g   = lane >> 2, s = lane & 3;
    const int cb0 = wid * 32;      // column-disjoint warps: B fragments not redundant

    const uint32_t sb0 = smem_u32(dsm);
    const float* Ab = adj  + (size_t)b * NN * NN;
    const float* Bx = g_xs + (size_t)b * NN * FF;

    // ---- tile loader (128 threads) ----
    auto load_tile = [&](int t) {
        int k0 = t * BKK;
        uint32_t sa = sb0 + (uint32_t)(AS_OFF_F + (t & 3) * AS_STG_F) * 4u;
        // A: 48 rows x 8 chunks = 384 cp16
        #pragma unroll
        for (int c = 0; c < 3; c++) {
            int ch = c * NTHR + tid;
            int row = ch >> 3, kc = ch & 7;
            int gr = m0 + row;
            int kk = k0 + kc * 4;
            int bytes = 16;
            if (gr >= NN) bytes = 0;
            int rem = (NN - kk) * 4;
            if (rem < 16) bytes = (rem > 0) ? (bytes < rem ? bytes : rem) : 0;
            const float* src = Ab + (size_t)(gr < NN ? gr : 0) * NN + (kk < NN ? kk : 0);
            cp16(sa + (uint32_t)(row * APITCH + kc * 4) * 4u, src, bytes);
        }
        uint32_t sbB = sb0 + (uint32_t)(BS_OFF_F + (t & 3) * BS_STG_F) * 4u;
        // B: 32 rows x 32 chunks = 1024 cp16
        #pragma unroll
        for (int c = 0; c < 8; c++) {
            int ch = c * NTHR + tid;
            int row = ch >> 5, nc = ch & 31;
            int kr = k0 + row;
            int bytes = (kr < NN) ? 16 : 0;
            const float* src = Bx + (size_t)(kr < NN ? kr : 0) * FF + nc * 4;
            cp16(sbB + (uint32_t)(row * BPITCH + nc * 4) * 4u, src, bytes);
        }
    };

    float acc[3][4][4];
    #pragma unroll
    for (int mt = 0; mt < 3; mt++)
        #pragma unroll
        for (int nt = 0; nt < 4; nt++)
            #pragma unroll
            for (int r = 0; r < 4; r++) acc[mt][nt][r] = 0.f;

    load_tile(0); cp_commit();
    load_tile(1); cp_commit();
    load_tile(2); cp_commit();

    for (int t = 0; t < NT; t++) {
        if (t + 3 < NT) load_tile(t + 3);
        cp_commit();
        asm volatile("cp.async.wait_group 3;" ::: "memory");
        __syncthreads();

        const float* As = dsm + AS_OFF_F + (t & 3) * AS_STG_F;
        const float* Bs = dsm + BS_OFF_F + (t & 3) * BS_STG_F;

        // double-buffered fragments across the 4 k8 sub-steps
        unsigned af[2][3][4];
        unsigned bf[2][4][2];

        auto load_frag = [&](int sub, int buf) {
            int ks = sub * 8;
            #pragma unroll
            for (int mt = 0; mt < 3; mt++) {
                int rb = mt * 16;
                af[buf][mt][0] = f2tf(As[(rb + g    ) * APITCH + ks + s    ]);
                af[buf][mt][1] = f2tf(As[(rb + g + 8) * APITCH + ks + s    ]);
                af[buf][mt][2] = f2tf(As[(rb + g    ) * APITCH + ks + s + 4]);
                af[buf][mt][3] = f2tf(As[(rb + g + 8) * APITCH + ks + s + 4]);
            }
            #pragma unroll
            for (int nt = 0; nt < 4; nt++) {
                int col = cb0 + nt * 8 + g;
                bf[buf][nt][0] = __float_as_uint(Bs[(ks + s    ) * BPITCH + col]);
                bf[buf][nt][1] = __float_as_uint(Bs[(ks + s + 4) * BPITCH + col]);
            }
        };

        load_frag(0, 0);
        #pragma unroll
        for (int sub = 0; sub < 4; sub++) {
            int cur = sub & 1;
            if (sub < 3) load_frag(sub + 1, cur ^ 1);
            #pragma unroll
            for (int nt = 0; nt < 4; nt++)
                #pragma unroll
                for (int mt = 0; mt < 3; mt++)
                    mma_tf32_frag(acc[mt][nt], af[cur][mt], bf[cur][nt][0], bf[cur][nt][1]);
        }
        __syncthreads();
    }

    // ---- theta -> smem (overlaps with support epilogue below) ----
    #pragma unroll
    for (int c = 0; c < 32; c++) {
        int ch = c * NTHR + tid;       // 0..4095
        int row = ch >> 5, nc = ch & 31;
        cp16(sb0 + (uint32_t)(TH_OFF_F + row * BPITCH + nc * 4) * 4u,
             theta + row * FF + nc * 4, 16);
    }
    cp_commit();

    // ---- support epilogue into smem S tile (fp32) ----
    const float alpha = alpha_p[0];
    const float oma   = 1.0f - alpha;
    float* S2 = dsm + S2_OFF_F;

    #pragma unroll
    for (int mt = 0; mt < 3; mt++) {
        #pragma unroll
        for (int half = 0; half < 2; half++) {
            int r  = mt * 16 + g + half * 8;             // local row 0..47
            int gr = m0 + r;
            bool ok = gr < NN;
            float di = ok ? g_dis[b * NN + gr] : 0.f;
            size_t base = ((size_t)b * NN + (ok ? gr : 0)) * FF;
            #pragma unroll
            for (int nt = 0; nt < 4; nt++) {
                int col = cb0 + nt * 8 + s * 2;
                float2 xsv = ok ? *reinterpret_cast<const float2*>(g_xs + base + col)
                                : make_float2(0.f, 0.f);
                float2 hv  = ok ? *reinterpret_cast<const float2*>(h0g + base + col)
                                : make_float2(0.f, 0.f);
                float c0 = acc[mt][nt][half * 2 + 0];
                float c1 = acc[mt][nt][half * 2 + 1];
                S2[r * S2PITCH + col    ] = oma * di * (c0 + xsv.x) + alpha * hv.x;
                S2[r * S2PITCH + col + 1] = oma * di * (c1 + xsv.y) + alpha * hv.y;
            }
        }
    }
    asm volatile("cp.async.wait_group 0;" ::: "memory");  // theta resident
    __syncthreads();

    // ---- second GEMM: D2 = S @ theta  (K = 128), reuse acc registers ----
    #pragma unroll
    for (int mt = 0; mt < 3; mt++)
        #pragma unroll
        for (int nt = 0; nt < 4; nt++)
            #pragma unroll
            for (int r = 0; r < 4; r++) acc[mt][nt][r] = 0.f;

    const float* TH = dsm + TH_OFF_F;
    #pragma unroll 4
    for (int sub = 0; sub < 16; sub++) {
        int ks = sub * 8;
        unsigned af2[3][4];
        #pragma unroll
        for (int mt = 0; mt < 3; mt++) {
            int rb = mt * 16;
            af2[mt][0] = __float_as_uint(S2[(rb + g    ) * S2PITCH + ks + s    ]);
            af2[mt][1] = __float_as_uint(S2[(rb + g + 8) * S2PITCH + ks + s    ]);
            af2[mt][2] = __float_as_uint(S2[(rb + g    ) * S2PITCH + ks + s + 4]);
            af2[mt][3] = __float_as_uint(S2[(rb + g + 8) * S2PITCH + ks + s + 4]);
        }
        #pragma unroll
        for (int nt = 0; nt < 4; nt++) {
            int col = cb0 + nt * 8 + g;
            unsigned b0 = __float_as_uint(TH[(ks + s    ) * BPITCH + col]);
            unsigned b1 = __float_as_uint(TH[(ks + s + 4) * BPITCH + col]);
            #pragma unroll
            for (int mt = 0; mt < 3; mt++)
                mma_tf32_frag(acc[mt][nt], af2[mt], b0, b1);
        }
    }

    // ---- final blend + store:  out = beta * D2 + (1-beta) * S ----
    const float beta = logf(lamda_p[0] / (float)l_p[0] + 1.0f);
    const float omb  = 1.0f - beta;

    #pragma unroll
    for (int mt = 0; mt < 3; mt++) {
        #pragma unroll
        for (int half = 0; half < 2; half++) {
            int r  = mt * 16 + g + half * 8;
            int gr = m0 + r;
            if (gr < NN) {
                size_t base = ((size_t)b * NN + gr) * FF;
                #pragma unroll
                for (int nt = 0; nt < 4; nt++) {
                    int col = cb0 + nt * 8 + s * 2;
                    float2 o;
                    o.x = beta * acc[mt][nt][half * 2 + 0] + omb * S2[r * S2PITCH + col    ];
                    o.y = beta * acc[mt][nt][half * 2 + 1] + omb * S2[r * S2PITCH + col + 1];
                    *reinterpret_cast<float2*>(out + base + col) = o;
                }
            }
        }
    }
}

// ---------------- launch ----------------
extern "C" void kernel_launch(void* const* d_in, const int* in_sizes, int n_in,
                              void* d_out, int out_size) {
    const float* x     = (const float*)d_in[0];
    const float* adj   = (const float*)d_in[1];
    const float* h0    = (const float*)d_in[2];
    const float* theta = (const float*)d_in[3];
    const float* lamda = (const float*)d_in[4];
    const float* alpha = (const float*)d_in[5];
    const int*   lptr  = (const int*)  d_in[6];

    cudaFuncSetAttribute(k_agg, cudaFuncAttributeMaxDynamicSharedMemorySize,
                         SMEM_F * 4);

    k_rowstats<<<BATCH * NN / 8, 256>>>(adj, x);
    dim3 g3((NN + BMM - 1) / BMM, BATCH);
    k_agg<<<g3, NTHR, SMEM_F * 4>>>(adj, h0, theta, lamda, alpha, lptr, (float*)d_out);
}

// round 12
// speedup vs baseline: 1.5365x; 1.5365x over previous
#include <cuda_runtime.h>
#include <cstdint>
#include <math.h>

// Problem constants
#define BATCH 4
#define NN    3000
#define FF    128

// ---------------- scratch (no allocations allowed) ----------------
__device__ __align__(128) float g_dis[BATCH * NN];        // d^{-1/2}
__device__ __align__(128) float g_xs [BATCH * NN * FF];   // tf32-rounded dis_j * x[j,f]

// ---------------- helpers ----------------
__device__ __forceinline__ uint32_t smem_u32(const void* p) {
    uint32_t a;
    asm("{ .reg .u64 t; cvta.to.shared.u64 t, %1; cvt.u32.u64 %0, t; }" : "=r"(a) : "l"(p));
    return a;
}
__device__ __forceinline__ unsigned f2tf(float f) {
    unsigned u;
    asm("cvt.rna.tf32.f32 %0, %1;" : "=r"(u) : "f"(f));
    return u;
}
__device__ __forceinline__ void cp16(uint32_t dst, const void* src, int bytes) {
    asm volatile("cp.async.cg.shared.global [%0], [%1], 16, %2;"
                 :: "r"(dst), "l"(src), "r"(bytes));
}
__device__ __forceinline__ void cp_commit() { asm volatile("cp.async.commit_group;" ::: "memory"); }

__device__ __forceinline__ void mma_tf32_frag(float* c, const unsigned* a, unsigned b0, unsigned b1) {
    asm volatile(
        "mma.sync.aligned.m16n8k8.row.col.f32.tf32.tf32.f32 "
        "{%0,%1,%2,%3}, {%4,%5,%6,%7}, {%8,%9}, {%0,%1,%2,%3};"
        : "+f"(c[0]), "+f"(c[1]), "+f"(c[2]), "+f"(c[3])
        : "r"(a[0]), "r"(a[1]), "r"(a[2]), "r"(a[3]), "r"(b0), "r"(b1));
}
__device__ __forceinline__ void ldsm_x4(unsigned* r, uint32_t addr) {
    asm volatile("ldmatrix.sync.aligned.m8n8.x4.shared.b16 {%0,%1,%2,%3}, [%4];"
                 : "=r"(r[0]), "=r"(r[1]), "=r"(r[2]), "=r"(r[3]) : "r"(addr));
}

// ---------------- Kernel 1: warp-per-row  deg -> d^{-1/2}, xs = tf32(dis_j*x) ----------------
__global__ __launch_bounds__(256) void k_rowstats(const float* __restrict__ adj,
                                                  const float* __restrict__ x) {
    int warp = threadIdx.x >> 5;
    int lane = threadIdx.x & 31;
    int row  = blockIdx.x * 8 + warp;          // 12000 rows, grid 1500
    const float4* a4 = reinterpret_cast<const float4*>(adj + (size_t)row * NN);

    float s = 0.f;
    #pragma unroll 4
    for (int i = lane; i < NN / 4; i += 32) {
        float4 v = a4[i];
        s += (v.x + v.y) + (v.z + v.w);
    }
    #pragma unroll
    for (int o = 16; o > 0; o >>= 1) s += __shfl_down_sync(0xffffffffu, s, o);
    float d = rsqrtf(__shfl_sync(0xffffffffu, s, 0) + 1.0f);
    if (lane == 0) g_dis[row] = d;

    float4 v = reinterpret_cast<const float4*>(x + (size_t)row * FF)[lane];
    v.x = __uint_as_float(f2tf(v.x * d));
    v.y = __uint_as_float(f2tf(v.y * d));
    v.z = __uint_as_float(f2tf(v.z * d));
    v.w = __uint_as_float(f2tf(v.w * d));
    reinterpret_cast<float4*>(g_xs + (size_t)row * FF)[lane] = v;
}

// ---------------- Kernel 2: fully fused aggregation + output ----------------
// R9 structure: BMM=96, 256 thr (8 warps, 2x4 grid, warp tile 48x32), BKK=32,
// 4-stage cp.async pipeline.  A fragments via ldmatrix.x4 (no cvt: HW RZ tf32),
// B pre-rounded RNA in k_rowstats.
#define BMM     96
#define BKK     32
#define NT      ((NN + BKK - 1) / BKK)     // 94
#define STAGES  4
#define APITCH  36                          // 144B rows: LDSM banks 0..31 distinct, 16B aligned
#define BPITCH  136                         // (8s+col)%32 distinct
#define S2PITCH 132                         // (4g+s)%32 distinct

#define AS_STG_F (BMM * APITCH)             // 3456
#define BS_STG_F (BKK * BPITCH)             // 4352
#define AS_OFF_F 0
#define BS_OFF_F (STAGES * AS_STG_F)        // 13824
#define SMEM_F   (BS_OFF_F + STAGES * BS_STG_F)  // 31232 floats = 124928 B
#define S2_OFF_F 0
#define TH_OFF_F 12672

__global__ __launch_bounds__(256, 1)
void k_agg(const float* __restrict__ adj,
           const float* __restrict__ h0g,
           const float* __restrict__ theta,
           const float* __restrict__ lamda_p,
           const float* __restrict__ alpha_p,
           const int* __restrict__ l_p,
           float* __restrict__ out) {
    extern __shared__ __align__(16) float dsm[];

    const int b   = blockIdx.y;
    const int m0  = blockIdx.x * BMM;
    const int tid = threadIdx.x;
    const int wid = tid >> 5, lane = tid & 31;
    const int g   = lane >> 2, s = lane & 3;
    const int wm  = wid >> 2;      // 0..1  -> 48-row half
    const int wn  = wid & 3;       // 0..3  -> 32-col quarter

    const uint32_t sb0 = smem_u32(dsm);
    const float* Ab = adj  + (size_t)b * NN * NN;
    const float* Bx = g_xs + (size_t)b * NN * FF;

    const int rb0 = wm * 48;
    const int cb0 = wn * 32;

    // ldmatrix lane mapping: matrices {rows +0/+8} x {k +0/+4}
    const int lds_row = rb0 + (lane & 7) + ((lane >> 3) & 1) * 8;
    const int lds_k   = (lane >> 4) * 4;
    const uint32_t lds_off = (uint32_t)(lds_row * APITCH + lds_k) * 4u;

    // ---- tile loader (256 threads) ----
    auto load_tile = [&](int t) {
        int k0 = t * BKK;
        uint32_t sa = sb0 + (uint32_t)(AS_OFF_F + (t & 3) * AS_STG_F) * 4u;
        // A: 96 rows x 8 chunks = 768 cp16
        #pragma unroll
        for (int c = 0; c < 3; c++) {
            int ch = c * 256 + tid;
            int row = ch >> 3, kc = ch & 7;
            int gr = m0 + row;
            int kk = k0 + kc * 4;
            int bytes = 16;
            if (gr >= NN) bytes = 0;
            int rem = (NN - kk) * 4;
            if (rem < 16) bytes = (rem > 0) ? (bytes < rem ? bytes : rem) : 0;
            const float* src = Ab + (size_t)(gr < NN ? gr : 0) * NN + (kk < NN ? kk : 0);
            cp16(sa + (uint32_t)(row * APITCH + kc * 4) * 4u, src, bytes);
        }
        uint32_t sbB = sb0 + (uint32_t)(BS_OFF_F + (t & 3) * BS_STG_F) * 4u;
        // B: 32 rows x 32 chunks = 1024 cp16
        #pragma unroll
        for (int c = 0; c < 4; c++) {
            int ch = c * 256 + tid;
            int row = ch >> 5, nc = ch & 31;
            int kr = k0 + row;
            int bytes = (kr < NN) ? 16 : 0;
            const float* src = Bx + (size_t)(kr < NN ? kr : 0) * FF + nc * 4;
            cp16(sbB + (uint32_t)(row * BPITCH + nc * 4) * 4u, src, bytes);
        }
    };

    float acc[3][4][4];
    #pragma unroll
    for (int mt = 0; mt < 3; mt++)
        #pragma unroll
        for (int nt = 0; nt < 4; nt++)
            #pragma unroll
            for (int r = 0; r < 4; r++) acc[mt][nt][r] = 0.f;

    load_tile(0); cp_commit();
    load_tile(1); cp_commit();
    load_tile(2); cp_commit();

    for (int t = 0; t < NT; t++) {
        if (t + 3 < NT) load_tile(t + 3);
        cp_commit();
        asm volatile("cp.async.wait_group 3;" ::: "memory");
        __syncthreads();

        const uint32_t saA = sb0 + (uint32_t)(AS_OFF_F + (t & 3) * AS_STG_F) * 4u + lds_off;
        const float* Bs = dsm + BS_OFF_F + (t & 3) * BS_STG_F;

        // double-buffered fragments across the 4 k8 sub-steps
        unsigned af[2][3][4];
        unsigned bf[2][4][2];

        auto load_frag = [&](int sub, int buf) {
            int ks = sub * 8;
            #pragma unroll
            for (int mt = 0; mt < 3; mt++)
                ldsm_x4(af[buf][mt], saA + (uint32_t)((mt * 16 * APITCH + ks) * 4));
            #pragma unroll
            for (int nt = 0; nt < 4; nt++) {
                int col = cb0 + nt * 8 + g;
                bf[buf][nt][0] = __float_as_uint(Bs[(ks + s    ) * BPITCH + col]);
                bf[buf][nt][1] = __float_as_uint(Bs[(ks + s + 4) * BPITCH + col]);
            }
        };

        load_frag(0, 0);
        #pragma unroll
        for (int sub = 0; sub < 4; sub++) {
            int cur = sub & 1;
            if (sub < 3) load_frag(sub + 1, cur ^ 1);
            #pragma unroll
            for (int nt = 0; nt < 4; nt++)
                #pragma unroll
                for (int mt = 0; mt < 3; mt++)
                    mma_tf32_frag(acc[mt][nt], af[cur][mt], bf[cur][nt][0], bf[cur][nt][1]);
        }
        __syncthreads();
    }

    // ---- theta -> smem (overlaps with support epilogue below) ----
    #pragma unroll
    for (int c = 0; c < 16; c++) {
        int ch = c * 256 + tid;        // 0..4095
        int row = ch >> 5, nc = ch & 31;
        cp16(sb0 + (uint32_t)(TH_OFF_F + row * BPITCH + nc * 4) * 4u,
             theta + row * FF + nc * 4, 16);
    }
    cp_commit();

    // ---- support epilogue into smem S tile (fp32) ----
    const float alpha = alpha_p[0];
    const float oma   = 1.0f - alpha;
    float* S2 = dsm + S2_OFF_F;

    #pragma unroll
    for (int mt = 0; mt < 3; mt++) {
        #pragma unroll
        for (int half = 0; half < 2; half++) {
            int r  = rb0 + mt * 16 + g + half * 8;       // local row 0..95
            int gr = m0 + r;
            bool ok = gr < NN;
            float di = ok ? g_dis[b * NN + gr] : 0.f;
            size_t base = ((size_t)b * NN + (ok ? gr : 0)) * FF;
            #pragma unroll
            for (int nt = 0; nt < 4; nt++) {
                int col = cb0 + nt * 8 + s * 2;
                float2 xsv = ok ? *reinterpret_cast<const float2*>(g_xs + base + col)
                                : make_float2(0.f, 0.f);
                float2 hv  = ok ? *reinterpret_cast<const float2*>(h0g + base + col)
                                : make_float2(0.f, 0.f);
                float c0 = acc[mt][nt][half * 2 + 0];
                float c1 = acc[mt][nt][half * 2 + 1];
                S2[r * S2PITCH + col    ] = oma * di * (c0 + xsv.x) + alpha * hv.x;
                S2[r * S2PITCH + col + 1] = oma * di * (c1 + xsv.y) + alpha * hv.y;
            }
        }
    }
    asm volatile("cp.async.wait_group 0;" ::: "memory");  // theta resident
    __syncthreads();

    // ---- second GEMM: D2 = S @ theta  (K = 128), reuse acc registers ----
    #pragma unroll
    for (int mt = 0; mt < 3; mt++)
        #pragma unroll
        for (int nt = 0; nt < 4; nt++)
            #pragma unroll
            for (int r = 0; r < 4; r++) acc[mt][nt][r] = 0.f;

    const float* TH = dsm + TH_OFF_F;
    #pragma unroll 4
    for (int sub = 0; sub < 16; sub++) {
        int ks = sub * 8;
        unsigned af2[3][4];
        #pragma unroll
        for (int mt = 0; mt < 3; mt++) {
            int rb = rb0 + mt * 16;
            af2[mt][0] = __float_as_uint(S2[(rb + g    ) * S2PITCH + ks + s    ]);
            af2[mt][1] = __float_as_uint(S2[(rb + g + 8) * S2PITCH + ks + s    ]);
            af2[mt][2] = __float_as_uint(S2[(rb + g    ) * S2PITCH + ks + s + 4]);
            af2[mt][3] = __float_as_uint(S2[(rb + g + 8) * S2PITCH + ks + s + 4]);
        }
        #pragma unroll
        for (int nt = 0; nt < 4; nt++) {
            int col = cb0 + nt * 8 + g;
            unsigned b0 = __float_as_uint(TH[(ks + s    ) * BPITCH + col]);
            unsigned b1 = __float_as_uint(TH[(ks + s + 4) * BPITCH + col]);
            #pragma unroll
            for (int mt = 0; mt < 3; mt++)
                mma_tf32_frag(acc[mt][nt], af2[mt], b0, b1);
        }
    }

    // ---- final blend + store:  out = beta * D2 + (1-beta) * S ----
    const float beta = logf(lamda_p[0] / (float)l_p[0] + 1.0f);
    const float omb  = 1.0f - beta;

    #pragma unroll
    for (int mt = 0; mt < 3; mt++) {
        #pragma unroll
        for (int half = 0; half < 2; half++) {
            int r  = rb0 + mt * 16 + g + half * 8;
            int gr = m0 + r;
            if (gr < NN) {
                size_t base = ((size_t)b * NN + gr) * FF;
                #pragma unroll
                for (int nt = 0; nt < 4; nt++) {
                    int col = cb0 + nt * 8 + s * 2;
                    float2 o;
                    o.x = beta * acc[mt][nt][half * 2 + 0] + omb * S2[r * S2PITCH + col    ];
                    o.y = beta * acc[mt][nt][half * 2 + 1] + omb * S2[r * S2PITCH + col + 1];
                    *reinterpret_cast<float2*>(out + base + col) = o;
                }
            }
        }
    }
}

// ---------------- launch ----------------
extern "C" void kernel_launch(void* const* d_in, const int* in_sizes, int n_in,
                              void* d_out, int out_size) {
    const float* x     = (const float*)d_in[0];
    const float* adj   = (const float*)d_in[1];
    const float* h0    = (const float*)d_in[2];
    const float* theta = (const float*)d_in[3];
    const float* lamda = (const float*)d_in[4];
    const float* alpha = (const float*)d_in[5];
    const int*   lptr  = (const int*)  d_in[6];

    cudaFuncSetAttribute(k_agg, cudaFuncAttributeMaxDynamicSharedMemorySize,
                         SMEM_F * 4);

    k_rowstats<<<BATCH * NN / 8, 256>>>(adj, x);
    dim3 g3((NN + BMM - 1) / BMM, BATCH);
    k_agg<<<g3, 256, SMEM_F * 4>>>(adj, h0, theta, lamda, alpha, lptr, (float*)d_out);
}

// round 13
// speedup vs baseline: 1.9429x; 1.2645x over previous
#include <cuda_runtime.h>
#include <cuda_fp16.h>
#include <cstdint>
#include <math.h>

// Problem constants
#define BATCH 4
#define NN    3000
#define FF    128

// ---------------- scratch (no allocations allowed) ----------------
__device__ __align__(128) float  g_dis [BATCH * NN];        // d^{-1/2}
__device__ __align__(128) __half g_adjh[(size_t)BATCH * NN * NN]; // fp16 adj (72MB)
__device__ __align__(128) __half g_xsh [BATCH * NN * FF];   // fp16 dis_j*x, row-major
__device__ __align__(128) __half g_xshT[BATCH * FF * NN];   // fp16, transposed [b][f][n]

// ---------------- helpers ----------------
__device__ __forceinline__ uint32_t smem_u32(const void* p) {
    uint32_t a;
    asm("{ .reg .u64 t; cvta.to.shared.u64 t, %1; cvt.u32.u64 %0, t; }" : "=r"(a) : "l"(p));
    return a;
}
__device__ __forceinline__ void cp16(uint32_t dst, const void* src, int bytes) {
    asm volatile("cp.async.cg.shared.global [%0], [%1], 16, %2;"
                 :: "r"(dst), "l"(src), "r"(bytes));
}
__device__ __forceinline__ void cp_commit() { asm volatile("cp.async.commit_group;" ::: "memory"); }

__device__ __forceinline__ void mma_f16(float* c, const unsigned* a, unsigned b0, unsigned b1) {
    asm volatile(
        "mma.sync.aligned.m16n8k16.row.col.f32.f16.f16.f32 "
        "{%0,%1,%2,%3}, {%4,%5,%6,%7}, {%8,%9}, {%0,%1,%2,%3};"
        : "+f"(c[0]), "+f"(c[1]), "+f"(c[2]), "+f"(c[3])
        : "r"(a[0]), "r"(a[1]), "r"(a[2]), "r"(a[3]), "r"(b0), "r"(b1));
}
__device__ __forceinline__ void mma_tf32_frag(float* c, const unsigned* a, unsigned b0, unsigned b1) {
    asm volatile(
        "mma.sync.aligned.m16n8k8.row.col.f32.tf32.tf32.f32 "
        "{%0,%1,%2,%3}, {%4,%5,%6,%7}, {%8,%9}, {%0,%1,%2,%3};"
        : "+f"(c[0]), "+f"(c[1]), "+f"(c[2]), "+f"(c[3])
        : "r"(a[0]), "r"(a[1]), "r"(a[2]), "r"(a[3]), "r"(b0), "r"(b1));
}
__device__ __forceinline__ void ldsm_x4(unsigned* r, uint32_t addr) {
    asm volatile("ldmatrix.sync.aligned.m8n8.x4.shared.b16 {%0,%1,%2,%3}, [%4];"
                 : "=r"(r[0]), "=r"(r[1]), "=r"(r[2]), "=r"(r[3]) : "r"(addr));
}

// ---------------- Kernel 1: warp-per-row: deg, fp16 adj copy, fp16 xs ----------------
__global__ __launch_bounds__(256) void k_rowstats(const float* __restrict__ adj,
                                                  const float* __restrict__ x) {
    int warp = threadIdx.x >> 5;
    int lane = threadIdx.x & 31;
    int row  = blockIdx.x * 8 + warp;          // 0..11999
    const float4* a4 = reinterpret_cast<const float4*>(adj + (size_t)row * NN);
    __half* ah = g_adjh + (size_t)row * NN;

    float s = 0.f;
    #pragma unroll 4
    for (int i = lane; i < NN / 4; i += 32) {
        float4 v = a4[i];
        s += (v.x + v.y) + (v.z + v.w);
        __half2 h01 = __floats2half2_rn(v.x, v.y);
        __half2 h23 = __floats2half2_rn(v.z, v.w);
        uint2 u;
        u.x = *reinterpret_cast<unsigned*>(&h01);
        u.y = *reinterpret_cast<unsigned*>(&h23);
        *reinterpret_cast<uint2*>(ah + 4 * i) = u;
    }
    #pragma unroll
    for (int o = 16; o > 0; o >>= 1) s += __shfl_down_sync(0xffffffffu, s, o);
    float d = rsqrtf(__shfl_sync(0xffffffffu, s, 0) + 1.0f);
    if (lane == 0) g_dis[row] = d;

    // xs (fp16, row-major): lane handles 4 features
    float4 v = reinterpret_cast<const float4*>(x + (size_t)row * FF)[lane];
    __half2 h01 = __floats2half2_rn(v.x * d, v.y * d);
    __half2 h23 = __floats2half2_rn(v.z * d, v.w * d);
    uint2 u;
    u.x = *reinterpret_cast<unsigned*>(&h01);
    u.y = *reinterpret_cast<unsigned*>(&h23);
    *reinterpret_cast<uint2*>(g_xsh + (size_t)row * FF + 4 * lane) = u;
}

// ---------------- Kernel 1b: fp16 transpose  xsT[b][f][n] = xs[b][n][f] ----------------
__global__ void k_xt() {
    __shared__ __half tile[32][40];
    int b  = blockIdx.z;
    int f0 = blockIdx.y * 32;
    int n0 = blockIdx.x * 32;
    int tx = threadIdx.x, ty = threadIdx.y;
    #pragma unroll
    for (int j = 0; j < 4; j++) {
        int n = n0 + ty + j * 8;
        __half v = __float2half(0.f);
        if (n < NN) v = g_xsh[((size_t)b * NN + n) * FF + f0 + tx];
        tile[ty + j * 8][tx] = v;
    }
    __syncthreads();
    #pragma unroll
    for (int j = 0; j < 4; j++) {
        int f = f0 + ty + j * 8;
        int n = n0 + tx;
        if (n < NN) g_xshT[((size_t)b * FF + f) * NN + n] = tile[tx][ty + j * 8];
    }
}

// ---------------- Kernel 2: fused fp16 aggregation + tf32 output GEMM ----------------
#define BMM     96
#define BKK     64
#define NT      ((NN + BKK - 1) / BKK)     // 47
#define APB     144                         // bytes per A row (128 + 16 pad): 16r%128 distinct
#define BPB     144                         // bytes per Bt row
#define A_STG_B (BMM * APB)                 // 13824
#define B_STG_B (128 * BPB)                 // 18432
#define STG_B   (A_STG_B + B_STG_B)         // 32256
// epilogue reuse (same as R12): S2 fp32 pitch 132 at 0; theta fp32 pitch 136 at float 12672
#define S2PITCH 132
#define THPITCH 136
#define TH_OFF_F 12672
#define SMEM_BYTES 120320                   // max(3*STG_B=96768, 50688+69632=120320)

__global__ __launch_bounds__(256, 1)
void k_agg(const float* __restrict__ h0g,
           const float* __restrict__ theta,
           const float* __restrict__ xg,
           const float* __restrict__ lamda_p,
           const float* __restrict__ alpha_p,
           const int* __restrict__ l_p,
           float* __restrict__ out) {
    extern __shared__ __align__(16) float dsm[];

    const int b   = blockIdx.y;
    const int m0  = blockIdx.x * BMM;
    const int tid = threadIdx.x;
    const int wid = tid >> 5, lane = tid & 31;
    const int g   = lane >> 2, s = lane & 3;
    const int wm  = wid >> 2;      // 0..1  -> 48-row half
    const int wn  = wid & 3;       // 0..3  -> 32-col quarter

    const uint32_t sb0 = smem_u32(dsm);
    const __half* Ab = g_adjh + (size_t)b * NN * NN;
    const __half* Bt = g_xshT + (size_t)b * FF * NN;

    const int rb0 = wm * 48;
    const int cb0 = wn * 32;

    // ldmatrix lane offsets (bytes)
    const uint32_t a_lane = (uint32_t)((lane & 15) * APB + (lane >> 4) * 16);
    const uint32_t b_lane = (uint32_t)(((lane & 7) + ((lane >> 4) << 3)) * BPB
                                       + ((lane >> 3) & 1) * 16);

    // ---- tile loader: A 96x8 chunks=768, B 128x8=1024 cp16 over 256 thr ----
    auto load_tile = [&](int t) {
        int k0 = t * BKK;
        uint32_t sa = sb0 + (uint32_t)((t % 3) * STG_B);
        #pragma unroll
        for (int c = 0; c < 3; c++) {
            int ch = c * 256 + tid;        // 0..767
            int row = ch >> 3, kc = ch & 7;
            int gr = m0 + row;
            int kk = k0 + kc * 8;          // half index
            int bytes = 16;
            if (gr >= NN) bytes = 0;
            int rem = (NN - kk) * 2;
            if (rem < 16) bytes = (rem > 0) ? (bytes < rem ? bytes : rem) : 0;
            const __half* src = Ab + (size_t)(gr < NN ? gr : 0) * NN + (kk < NN ? kk : 0);
            cp16(sa + (uint32_t)(row * APB + kc * 16), src, bytes);
        }
        uint32_t sbB = sa + A_STG_B;
        #pragma unroll
        for (int c = 0; c < 4; c++) {
            int ch = c * 256 + tid;        // 0..1023
            int f = ch >> 3, kc = ch & 7;
            int kk = k0 + kc * 8;
            int bytes = 16;
            int rem = (NN - kk) * 2;
            if (rem < 16) bytes = (rem > 0) ? (bytes < rem ? bytes : rem) : 0;
            const __half* src = Bt + (size_t)f * NN + (kk < NN ? kk : 0);
            cp16(sbB + (uint32_t)(f * BPB + kc * 16), src, bytes);
        }
    };

    float acc[3][4][4];
    #pragma unroll
    for (int mt = 0; mt < 3; mt++)
        #pragma unroll
        for (int nt = 0; nt < 4; nt++)
            #pragma unroll
            for (int r = 0; r < 4; r++) acc[mt][nt][r] = 0.f;

    load_tile(0); cp_commit();
    load_tile(1); cp_commit();

    for (int t = 0; t < NT; t++) {
        if (t + 2 < NT) load_tile(t + 2);
        cp_commit();
        asm volatile("cp.async.wait_group 2;" ::: "memory");
        __syncthreads();

        const uint32_t sa  = sb0 + (uint32_t)((t % 3) * STG_B);
        const uint32_t saA = sa + a_lane + (uint32_t)(rb0 * APB);
        const uint32_t saB = sa + A_STG_B + b_lane + (uint32_t)(cb0 * BPB);

        unsigned af[2][3][4];
        unsigned bf[2][2][4];   // [buf][ntp][4]: {b0(2ntp),b1(2ntp),b0(2ntp+1),b1(2ntp+1)}

        auto load_frag = [&](int sub, int buf) {
            uint32_t ko = (uint32_t)(sub * 32);    // 16 halfs
            #pragma unroll
            for (int mt = 0; mt < 3; mt++)
                ldsm_x4(af[buf][mt], saA + (uint32_t)(mt * 16 * APB) + ko);
            #pragma unroll
            for (int ntp = 0; ntp < 2; ntp++)
                ldsm_x4(bf[buf][ntp], saB + (uint32_t)(ntp * 16 * BPB) + ko);
        };

        load_frag(0, 0);
        #pragma unroll
        for (int sub = 0; sub < 4; sub++) {
            int cur = sub & 1;
            if (sub < 3) load_frag(sub + 1, cur ^ 1);
            #pragma unroll
            for (int ntp = 0; ntp < 2; ntp++)
                #pragma unroll
                for (int h = 0; h < 2; h++)
                    #pragma unroll
                    for (int mt = 0; mt < 3; mt++)
                        mma_f16(acc[mt][ntp * 2 + h], af[cur][mt],
                                bf[cur][ntp][h * 2], bf[cur][ntp][h * 2 + 1]);
        }
        __syncthreads();
    }

    // ---- theta -> smem (fp32, overlaps epilogue) ----
    #pragma unroll
    for (int c = 0; c < 16; c++) {
        int ch = c * 256 + tid;        // 0..4095
        int row = ch >> 5, nc = ch & 31;
        cp16(sb0 + (uint32_t)((TH_OFF_F + row * THPITCH + nc * 4) * 4),
             theta + row * FF + nc * 4, 16);
    }
    cp_commit();

    // ---- support epilogue into smem S tile (fp32) ----
    // S = oma*di*c + oma*di*di*x + alpha*h0
    const float alpha = alpha_p[0];
    const float oma   = 1.0f - alpha;
    float* S2 = dsm;

    #pragma unroll
    for (int mt = 0; mt < 3; mt++) {
        #pragma unroll
        for (int half = 0; half < 2; half++) {
            int r  = rb0 + mt * 16 + g + half * 8;       // local row 0..95
            int gr = m0 + r;
            bool ok = gr < NN;
            float di = ok ? g_dis[b * NN + gr] : 0.f;
            float c1f = oma * di;
            float c2f = c1f * di;
            size_t base = ((size_t)b * NN + (ok ? gr : 0)) * FF;
            #pragma unroll
            for (int nt = 0; nt < 4; nt++) {
                int col = cb0 + nt * 8 + s * 2;
                float2 xv = ok ? *reinterpret_cast<const float2*>(xg + base + col)
                               : make_float2(0.f, 0.f);
                float2 hv = ok ? *reinterpret_cast<const float2*>(h0g + base + col)
                               : make_float2(0.f, 0.f);
                float c0 = acc[mt][nt][half * 2 + 0];
                float c1 = acc[mt][nt][half * 2 + 1];
                S2[r * S2PITCH + col    ] = c1f * c0 + c2f * xv.x + alpha * hv.x;
                S2[r * S2PITCH + col + 1] = c1f * c1 + c2f * xv.y + alpha * hv.y;
            }
        }
    }
    asm volatile("cp.async.wait_group 0;" ::: "memory");  // theta resident
    __syncthreads();

    // ---- second GEMM: D2 = S @ theta  (tf32, K = 128), reuse acc regs ----
    #pragma unroll
    for (int mt = 0; mt < 3; mt++)
        #pragma unroll
        for (int nt = 0; nt < 4; nt++)
            #pragma unroll
            for (int r = 0; r < 4; r++) acc[mt][nt][r] = 0.f;

    const float* TH = dsm + TH_OFF_F;
    #pragma unroll 4
    for (int sub = 0; sub < 16; sub++) {
        int ks = sub * 8;
        unsigned af2[3][4];
        #pragma unroll
        for (int mt = 0; mt < 3; mt++) {
            int rb = rb0 + mt * 16;
            af2[mt][0] = __float_as_uint(S2[(rb + g    ) * S2PITCH + ks + s    ]);
            af2[mt][1] = __float_as_uint(S2[(rb + g + 8) * S2PITCH + ks + s    ]);
            af2[mt][2] = __float_as_uint(S2[(rb + g    ) * S2PITCH + ks + s + 4]);
            af2[mt][3] = __float_as_uint(S2[(rb + g + 8) * S2PITCH + ks + s + 4]);
        }
        #pragma unroll
        for (int nt = 0; nt < 4; nt++) {
            int col = cb0 + nt * 8 + g;
            unsigned b0 = __float_as_uint(TH[(ks + s    ) * THPITCH + col]);
            unsigned b1 = __float_as_uint(TH[(ks + s + 4) * THPITCH + col]);
            #pragma unroll
            for (int mt = 0; mt < 3; mt++)
                mma_tf32_frag(acc[mt][nt], af2[mt], b0, b1);
        }
    }

    // ---- final blend + store:  out = beta * D2 + (1-beta) * S ----
    const float beta = logf(lamda_p[0] / (float)l_p[0] + 1.0f);
    const float omb  = 1.0f - beta;

    #pragma unroll
    for (int mt = 0; mt < 3; mt++) {
        #pragma unroll
        for (int half = 0; half < 2; half++) {
            int r  = rb0 + mt * 16 + g + half * 8;
            int gr = m0 + r;
            if (gr < NN) {
                size_t base = ((size_t)b * NN + gr) * FF;
                #pragma unroll
                for (int nt = 0; nt < 4; nt++) {
                    int col = cb0 + nt * 8 + s * 2;
                    float2 o;
                    o.x = beta * acc[mt][nt][half * 2 + 0] + omb * S2[r * S2PITCH + col    ];
                    o.y = beta * acc[mt][nt][half * 2 + 1] + omb * S2[r * S2PITCH + col + 1];
                    *reinterpret_cast<float2*>(out + base + col) = o;
                }
            }
        }
    }
}

// ---------------- launch ----------------
extern "C" void kernel_launch(void* const* d_in, const int* in_sizes, int n_in,
                              void* d_out, int out_size) {
    const float* x     = (const float*)d_in[0];
    const float* adj   = (const float*)d_in[1];
    const float* h0    = (const float*)d_in[2];
    const float* theta = (const float*)d_in[3];
    const float* lamda = (const float*)d_in[4];
    const float* alpha = (const float*)d_in[5];
    const int*   lptr  = (const int*)  d_in[6];

    cudaFuncSetAttribute(k_agg, cudaFuncAttributeMaxDynamicSharedMemorySize,
                         SMEM_BYTES);

    k_rowstats<<<BATCH * NN / 8, 256>>>(adj, x);
    k_xt<<<dim3((NN + 31) / 32, FF / 32, BATCH), dim3(32, 8)>>>();
    dim3 g3((NN + BMM - 1) / BMM, BATCH);
    k_agg<<<g3, 256, SMEM_BYTES>>>(h0, theta, x, lamda, alpha, lptr, (float*)d_out);
}

// round 17
// speedup vs baseline: 2.0235x; 1.0415x over previous
#include <cuda_runtime.h>
#include <cuda_fp16.h>
#include <cstdint>
#include <math.h>

// Problem constants
#define BATCH 4
#define NN    3000
#define FF    128

// ---------------- scratch (no allocations allowed) ----------------
__device__ __align__(128) float  g_dis [BATCH * NN];        // d^{-1/2}
__device__ __align__(128) __half g_adjh[(size_t)BATCH * NN * NN]; // fp16 adj (72MB)
__device__ __align__(128) __half g_xsh [BATCH * NN * FF];   // fp16 dis_j*x, row-major
__device__ __align__(128) __half g_xshT[BATCH * FF * NN];   // fp16, transposed [b][f][n]

// ---------------- helpers ----------------
__device__ __forceinline__ uint32_t smem_u32(const void* p) {
    uint32_t a;
    asm("{ .reg .u64 t; cvta.to.shared.u64 t, %1; cvt.u32.u64 %0, t; }" : "=r"(a) : "l"(p));
    return a;
}
__device__ __forceinline__ void cp16(uint32_t dst, const void* src, int bytes) {
    asm volatile("cp.async.cg.shared.global [%0], [%1], 16, %2;"
                 :: "r"(dst), "l"(src), "r"(bytes));
}
__device__ __forceinline__ void cp_commit() { asm volatile("cp.async.commit_group;" ::: "memory"); }

__device__ __forceinline__ void mma_f16(float* c, const unsigned* a, unsigned b0, unsigned b1) {
    asm volatile(
        "mma.sync.aligned.m16n8k16.row.col.f32.f16.f16.f32 "
        "{%0,%1,%2,%3}, {%4,%5,%6,%7}, {%8,%9}, {%0,%1,%2,%3};"
        : "+f"(c[0]), "+f"(c[1]), "+f"(c[2]), "+f"(c[3])
        : "r"(a[0]), "r"(a[1]), "r"(a[2]), "r"(a[3]), "r"(b0), "r"(b1));
}
__device__ __forceinline__ void mma_tf32_frag(float* c, const unsigned* a, unsigned b0, unsigned b1) {
    asm volatile(
        "mma.sync.aligned.m16n8k8.row.col.f32.tf32.tf32.f32 "
        "{%0,%1,%2,%3}, {%4,%5,%6,%7}, {%8,%9}, {%0,%1,%2,%3};"
        : "+f"(c[0]), "+f"(c[1]), "+f"(c[2]), "+f"(c[3])
        : "r"(a[0]), "r"(a[1]), "r"(a[2]), "r"(a[3]), "r"(b0), "r"(b1));
}
__device__ __forceinline__ void ldsm_x4(unsigned* r, uint32_t addr) {
    asm volatile("ldmatrix.sync.aligned.m8n8.x4.shared.b16 {%0,%1,%2,%3}, [%4];"
                 : "=r"(r[0]), "=r"(r[1]), "=r"(r[2]), "=r"(r[3]) : "r"(addr));
}

// ---------------- Kernel 1: warp-per-row: deg, fp16 adj copy, fp16 xs ----------------
__global__ __launch_bounds__(256) void k_rowstats(const float* __restrict__ adj,
                                                  const float* __restrict__ x) {
    int warp = threadIdx.x >> 5;
    int lane = threadIdx.x & 31;
    int row  = blockIdx.x * 8 + warp;          // 0..11999
    const float4* a4 = reinterpret_cast<const float4*>(adj + (size_t)row * NN);
    __half* ah = g_adjh + (size_t)row * NN;

    float s = 0.f;
    #pragma unroll 4
    for (int i = lane; i < NN / 4; i += 32) {
        float4 v = a4[i];
        s += (v.x + v.y) + (v.z + v.w);
        __half2 h01 = __floats2half2_rn(v.x, v.y);
        __half2 h23 = __floats2half2_rn(v.z, v.w);
        uint2 u;
        u.x = *reinterpret_cast<unsigned*>(&h01);
        u.y = *reinterpret_cast<unsigned*>(&h23);
        *reinterpret_cast<uint2*>(ah + 4 * i) = u;
    }
    #pragma unroll
    for (int o = 16; o > 0; o >>= 1) s += __shfl_down_sync(0xffffffffu, s, o);
    float d = rsqrtf(__shfl_sync(0xffffffffu, s, 0) + 1.0f);
    if (lane == 0) g_dis[row] = d;

    float4 v = reinterpret_cast<const float4*>(x + (size_t)row * FF)[lane];
    __half2 h01 = __floats2half2_rn(v.x * d, v.y * d);
    __half2 h23 = __floats2half2_rn(v.z * d, v.w * d);
    uint2 u;
    u.x = *reinterpret_cast<unsigned*>(&h01);
    u.y = *reinterpret_cast<unsigned*>(&h23);
    *reinterpret_cast<uint2*>(g_xsh + (size_t)row * FF + 4 * lane) = u;
}

// ---------------- Kernel 1b: fp16 transpose  xsT[b][f][n] = xs[b][n][f] ----------------
__global__ void k_xt() {
    __shared__ __half tile[32][40];
    int b  = blockIdx.z;
    int f0 = blockIdx.y * 32;
    int n0 = blockIdx.x * 32;
    int tx = threadIdx.x, ty = threadIdx.y;
    #pragma unroll
    for (int j = 0; j < 4; j++) {
        int n = n0 + ty + j * 8;
        __half v = __float2half(0.f);
        if (n < NN) v = g_xsh[((size_t)b * NN + n) * FF + f0 + tx];
        tile[ty + j * 8][tx] = v;
    }
    __syncthreads();
    #pragma unroll
    for (int j = 0; j < 4; j++) {
        int f = f0 + ty + j * 8;
        int n = n0 + tx;
        if (n < NN) g_xshT[((size_t)b * FF + f) * NN + n] = tile[tx][ty + j * 8];
    }
}

// ---------------- Kernel 2: fused fp16 aggregation + tf32 output GEMM ----------------
#define BMM     96
#define BKK     128
#define NT      ((NN + BKK - 1) / BKK)     // 24
#define APB     272                         // bytes per A row (256 + 16 pad)
#define BPB     272                         // bytes per Bt row
#define A_STG_B (BMM * APB)                 // 26112
#define B_STG_B (128 * BPB)                 // 34816
#define STG_B   (A_STG_B + B_STG_B)         // 60928
#define S2PITCH 132
#define THPITCH 136
#define TH_OFF_F 12672
#define SMEM_BYTES (3 * STG_B)              // 182784 (>= 120320 epilogue reuse)

__global__ __launch_bounds__(256, 1)
void k_agg(const float* __restrict__ h0g,
           const float* __restrict__ theta,
           const float* __restrict__ xg,
           const float* __restrict__ lamda_p,
           const float* __restrict__ alpha_p,
           const int* __restrict__ l_p,
           float* __restrict__ out) {
    extern __shared__ __align__(16) float dsm[];

    const int b   = blockIdx.y;
    const int m0  = blockIdx.x * BMM;
    const int tid = threadIdx.x;
    const int wid = tid >> 5, lane = tid & 31;
    const int g   = lane >> 2, s = lane & 3;
    const int wm  = wid >> 2;      // 0..1  -> 48-row half
    const int wn  = wid & 3;       // 0..3  -> 32-col quarter

    const uint32_t sb0 = smem_u32(dsm);
    const __half* Ab = g_adjh + (size_t)b * NN * NN;
    const __half* Bt = g_xshT + (size_t)b * FF * NN;

    const int rb0 = wm * 48;
    const int cb0 = wn * 32;

    // ldmatrix lane offsets (bytes)
    const uint32_t a_lane = (uint32_t)((lane & 15) * APB + (lane >> 4) * 16);
    const uint32_t b_lane = (uint32_t)(((lane & 7) + ((lane >> 4) << 3)) * BPB
                                       + ((lane >> 3) & 1) * 16);

    // ---- tile loader: A 96x16 chunks=1536, B 128x16=2048 cp16 over 256 thr ----
    auto load_tile = [&](int t) {
        int k0 = t * BKK;
        uint32_t sa = sb0 + (uint32_t)((t % 3) * STG_B);
        #pragma unroll
        for (int c = 0; c < 6; c++) {
            int ch = c * 256 + tid;        // 0..1535
            int row = ch >> 4, kc = ch & 15;
            int gr = m0 + row;
            int kk = k0 + kc * 8;          // half index
            int bytes = 16;
            if (gr >= NN) bytes = 0;
            int rem = (NN - kk) * 2;
            if (rem < 16) bytes = (rem > 0) ? (bytes < rem ? bytes : rem) : 0;
            const __half* src = Ab + (size_t)(gr < NN ? gr : 0) * NN + (kk < NN ? kk : 0);
            cp16(sa + (uint32_t)(row * APB + kc * 16), src, bytes);
        }
        uint32_t sbB = sa + A_STG_B;
        #pragma unroll
        for (int c = 0; c < 8; c++) {
            int ch = c * 256 + tid;        // 0..2047
            int f = ch >> 4, kc = ch & 15;
            int kk = k0 + kc * 8;
            int bytes = 16;
            int rem = (NN - kk) * 2;
            if (rem < 16) bytes = (rem > 0) ? (bytes < rem ? bytes : rem) : 0;
            const __half* src = Bt + (size_t)f * NN + (kk < NN ? kk : 0);
            cp16(sbB + (uint32_t)(f * BPB + kc * 16), src, bytes);
        }
    };

    float acc[3][4][4];
    #pragma unroll
    for (int mt = 0; mt < 3; mt++)
        #pragma unroll
        for (int nt = 0; nt < 4; nt++)
            #pragma unroll
            for (int r = 0; r < 4; r++) acc[mt][nt][r] = 0.f;

    load_tile(0); cp_commit();
    load_tile(1); cp_commit();

    for (int t = 0; t < NT; t++) {
        // tile t resident; all warps done computing buffer (t+2)%3's old contents
        asm volatile("cp.async.wait_group 1;" ::: "memory");
        __syncthreads();
        if (t + 2 < NT) { load_tile(t + 2); }
        cp_commit();

        const uint32_t sa  = sb0 + (uint32_t)((t % 3) * STG_B);
        const uint32_t saA = sa + a_lane + (uint32_t)(rb0 * APB);
        const uint32_t saB = sa + A_STG_B + b_lane + (uint32_t)(cb0 * BPB);

        unsigned af[2][3][4];
        unsigned bf[2][2][4];

        auto load_frag = [&](int sub, int buf) {
            uint32_t ko = (uint32_t)(sub * 32);    // 16 halfs
            #pragma unroll
            for (int mt = 0; mt < 3; mt++)
                ldsm_x4(af[buf][mt], saA + (uint32_t)(mt * 16 * APB) + ko);
            #pragma unroll
            for (int ntp = 0; ntp < 2; ntp++)
                ldsm_x4(bf[buf][ntp], saB + (uint32_t)(ntp * 16 * BPB) + ko);
        };

        load_frag(0, 0);
        #pragma unroll
        for (int sub = 0; sub < 8; sub++) {
            int cur = sub & 1;
            if (sub < 7) load_frag(sub + 1, cur ^ 1);
            #pragma unroll
            for (int ntp = 0; ntp < 2; ntp++)
                #pragma unroll
                for (int h = 0; h < 2; h++)
                    #pragma unroll
                    for (int mt = 0; mt < 3; mt++)
                        mma_f16(acc[mt][ntp * 2 + h], af[cur][mt],
                                bf[cur][ntp][h * 2], bf[cur][ntp][h * 2 + 1]);
        }
    }
    __syncthreads();   // all compute done before epilogue overwrites smem

    // ---- theta -> smem (fp32, overlaps epilogue) ----
    #pragma unroll
    for (int c = 0; c < 16; c++) {
        int ch = c * 256 + tid;        // 0..4095
        int row = ch >> 5, nc = ch & 31;
        cp16(sb0 + (uint32_t)((TH_OFF_F + row * THPITCH + nc * 4) * 4),
             theta + row * FF + nc * 4, 16);
    }
    cp_commit();

    // ---- support epilogue into smem S tile (fp32) ----
    const float alpha = alpha_p[0];
    const float oma   = 1.0f - alpha;
    float* S2 = dsm;

    #pragma unroll
    for (int mt = 0; mt < 3; mt++) {
        #pragma unroll
        for (int half = 0; half < 2; half++) {
            int r  = rb0 + mt * 16 + g + half * 8;       // local row 0..95
            int gr = m0 + r;
            bool ok = gr < NN;
            float di = ok ? g_dis[b * NN + gr] : 0.f;
            float c1f = oma * di;
            float c2f = c1f * di;
            size_t base = ((size_t)b * NN + (ok ? gr : 0)) * FF;
            #pragma unroll
            for (int nt = 0; nt < 4; nt++) {
                int col = cb0 + nt * 8 + s * 2;
                float2 xv = ok ? *reinterpret_cast<const float2*>(xg + base + col)
                               : make_float2(0.f, 0.f);
                float2 hv = ok ? *reinterpret_cast<const float2*>(h0g + base + col)
                               : make_float2(0.f, 0.f);
                float c0 = acc[mt][nt][half * 2 + 0];
                float c1 = acc[mt][nt][half * 2 + 1];
                S2[r * S2PITCH + col    ] = c1f * c0 + c2f * xv.x + alpha * hv.x;
                S2[r * S2PITCH + col + 1] = c1f * c1 + c2f * xv.y + alpha * hv.y;
            }
        }
    }
    asm volatile("cp.async.wait_group 0;" ::: "memory");  // theta resident
    __syncthreads();

    // ---- second GEMM: D2 = S @ theta  (tf32, K = 128), reuse acc regs ----
    #pragma unroll
    for (int mt = 0; mt < 3; mt++)
        #pragma unroll
        for (int nt = 0; nt < 4; nt++)
            #pragma unroll
            for (int r = 0; r < 4; r++) acc[mt][nt][r] = 0.f;

    const float* TH = dsm + TH_OFF_F;
    #pragma unroll 4
    for (int sub = 0; sub < 16; sub++) {
        int ks = sub * 8;
        unsigned af2[3][4];
        #pragma unroll
        for (int mt = 0; mt < 3; mt++) {
            int rb = rb0 + mt * 16;
            af2[mt][0] = __float_as_uint(S2[(rb + g    ) * S2PITCH + ks + s    ]);
            af2[mt][1] = __float_as_uint(S2[(rb + g + 8) * S2PITCH + ks + s    ]);
            af2[mt][2] = __float_as_uint(S2[(rb + g    ) * S2PITCH + ks + s + 4]);
            af2[mt][3] = __float_as_uint(S2[(rb + g + 8) * S2PITCH + ks + s + 4]);
        }
        #pragma unroll
        for (int nt = 0; nt < 4; nt++) {
            int col = cb0 + nt * 8 + g;
            unsigned b0 = __float_as_uint(TH[(ks + s    ) * THPITCH + col]);
            unsigned b1 = __float_as_uint(TH[(ks + s + 4) * THPITCH + col]);
            #pragma unroll
            for (int mt = 0; mt < 3; mt++)
                mma_tf32_frag(acc[mt][nt], af2[mt], b0, b1);
        }
    }

    // ---- final blend + store:  out = beta * D2 + (1-beta) * S ----
    const float beta = logf(lamda_p[0] / (float)l_p[0] + 1.0f);
    const float omb  = 1.0f - beta;

    #pragma unroll
    for (int mt = 0; mt < 3; mt++) {
        #pragma unroll
        for (int half = 0; half < 2; half++) {
            int r  = rb0 + mt * 16 + g + half * 8;
            int gr = m0 + r;
            if (gr < NN) {
                size_t base = ((size_t)b * NN + gr) * FF;
                #pragma unroll
                for (int nt = 0; nt < 4; nt++) {
                    int col = cb0 + nt * 8 + s * 2;
                    float2 o;
                    o.x = beta * acc[mt][nt][half * 2 + 0] + omb * S2[r * S2PITCH + col    ];
                    o.y = beta * acc[mt][nt][half * 2 + 1] + omb * S2[r * S2PITCH + col + 1];
                    *reinterpret_cast<float2*>(out + base + col) = o;
                }
            }
        }
    }
}

// ---------------- launch ----------------
extern "C" void kernel_launch(void* const* d_in, const int* in_sizes, int n_in,
                              void* d_out, int out_size) {
    const float* x     = (const float*)d_in[0];
    const float* adj   = (const float*)d_in[1];
    const float* h0    = (const float*)d_in[2];
    const float* theta = (const float*)d_in[3];
    const float* lamda = (const float*)d_in[4];
    const float* alpha = (const float*)d_in[5];
    const int*   lptr  = (const int*)  d_in[6];

    cudaFuncSetAttribute(k_agg, cudaFuncAttributeMaxDynamicSharedMemorySize,
                         SMEM_BYTES);

    k_rowstats<<<BATCH * NN / 8, 256>>>(adj, x);
    k_xt<<<dim3((NN + 31) / 32, FF / 32, BATCH), dim3(32, 8)>>>();
    dim3 g3((NN + BMM - 1) / BMM, BATCH);
    k_agg<<<g3, 256, SMEM_BYTES>>>(h0, theta, x, lamda, alpha, lptr, (float*)d_out);
}